// round 1
// baseline (speedup 1.0000x reference)
#include <cuda_runtime.h>

#define NN 50000
#define NE 800000
#define DD 128

// ---------------- scratch (__device__ globals; no allocation allowed) ----------------
__device__ float d_Z[(size_t)NN * DD];     // z = x @ W for current layer
__device__ float d_X[(size_t)NN * DD];     // layer outputs ping
__device__ float d_Y[(size_t)NN * DD];     // layer outputs pong
__device__ float d_Ssrc[NN];
__device__ float d_Sdst[NN];
__device__ float d_esc[NE];                // per-edge scratch (e, then exp(e-m))
__device__ int   d_deg[NN];
__device__ int   d_cur[NN];
__device__ int   d_off[NN + 1];
__device__ int   d_csrsrc[NE];             // src node per CSR slot (grouped by dst)
__device__ float d_gsum[DD];

// ---------------- helpers ----------------
__device__ __forceinline__ unsigned long long packdup(float x) {
    unsigned long long r;
    asm("mov.b64 %0,{%1,%1};" : "=l"(r) : "f"(x));
    return r;
}
__device__ __forceinline__ void unpack2(unsigned long long v, float& x, float& y) {
    asm("mov.b64 {%0,%1},%2;" : "=f"(x), "=f"(y) : "l"(v));
}
__device__ __forceinline__ void ffma2(unsigned long long& d, unsigned long long a, unsigned long long b) {
    asm("fma.rn.f32x2 %0,%1,%2,%0;" : "+l"(d) : "l"(a), "l"(b));
}
__device__ __forceinline__ float elu1(float x) {
    return x > 0.f ? x : expm1f(x);
}

// ---------------- init ----------------
__global__ void init_kernel(int* deg, float* gsum) {
    int i = blockIdx.x * blockDim.x + threadIdx.x;
    if (i < NN) deg[i] = 0;
    if (i < DD) gsum[i] = 0.f;
}

// ---------------- CSR build ----------------
__global__ void hist_kernel(const int* __restrict__ dst, int* __restrict__ deg) {
    int e = blockIdx.x * blockDim.x + threadIdx.x;
    if (e < NE) atomicAdd(&deg[dst[e]], 1);
}

__global__ void scan_kernel(const int* __restrict__ deg, int* __restrict__ off, int* __restrict__ cur) {
    __shared__ int ssum[1024];
    int t = threadIdx.x;
    const int CH = 49;  // 1024*49 = 50176 >= 50000
    int base = t * CH;
    int s = 0;
    for (int i = 0; i < CH; i++) {
        int idx = base + i;
        if (idx < NN) s += deg[idx];
    }
    ssum[t] = s;
    __syncthreads();
    int own = s;
    for (int o = 1; o < 1024; o <<= 1) {
        int v = (t >= o) ? ssum[t - o] : 0;
        __syncthreads();
        ssum[t] += v;
        __syncthreads();
    }
    int run = ssum[t] - own;  // exclusive prefix at chunk start
    for (int i = 0; i < CH; i++) {
        int idx = base + i;
        if (idx < NN) {
            off[idx] = run;
            cur[idx] = run;
            run += deg[idx];
        }
    }
    if (t == 1023) off[NN] = ssum[1023];
}

__global__ void scatter_kernel(const int* __restrict__ src, const int* __restrict__ dst,
                               int* __restrict__ cur, int* __restrict__ csrsrc) {
    int e = blockIdx.x * blockDim.x + threadIdx.x;
    if (e < NE) {
        int p = atomicAdd(&cur[dst[e]], 1);
        csrsrc[p] = src[e];
    }
}

// ---------------- GEMM: Z = Hin @ W, plus s_src/s_dst = Z @ a_lo / a_hi ----------------
// 64 rows per block (8 warps x 8 rows), W resident in smem (64KB), h staged
// transposed so row pairs are one LDS.64, compute via packed fma.rn.f32x2.
#define HS_STRIDE 66
#define GEMM_SMEM_FLOATS (16384 + DD * HS_STRIDE)
#define GEMM_SMEM_BYTES (GEMM_SMEM_FLOATS * 4)

__global__ void gemm_kernel(const float* __restrict__ Hin, const float* __restrict__ W,
                            const float* __restrict__ av, float* __restrict__ Zout,
                            float* __restrict__ Ss, float* __restrict__ Sd) {
    extern __shared__ float sm[];
    float* Ws = sm;                 // [128][128]
    float* Hs = sm + 16384;         // [k][row], stride HS_STRIDE

    int tid = threadIdx.x;
    int lane = tid & 31;
    int w = tid >> 5;

    // load W (row-major, W[k][j]) into shared
    for (int i = tid; i < 4096; i += 256)
        ((float4*)Ws)[i] = ((const float4*)W)[i];

    int row0 = blockIdx.x * 64;
    // stage h tile transposed: Hs[k * HS_STRIDE + r] = h[row0 + r][k]
    for (int i = tid; i < 8192; i += 256) {
        int r = i >> 7;
        int k = i & 127;
        int row = row0 + r;
        Hs[k * HS_STRIDE + r] = (row < NN) ? Hin[(size_t)row * DD + k] : 0.f;
    }
    __syncthreads();

    unsigned long long acc[4][4];
#pragma unroll
    for (int p = 0; p < 4; p++)
#pragma unroll
        for (int c = 0; c < 4; c++) acc[p][c] = 0ull;

    int hbase = w * 8;  // this warp's 8 rows within the tile
#pragma unroll 4
    for (int k = 0; k < 128; k++) {
        float4 wv = *(float4*)&Ws[k * DD + lane * 4];
        unsigned long long w0 = packdup(wv.x);
        unsigned long long w1 = packdup(wv.y);
        unsigned long long w2 = packdup(wv.z);
        unsigned long long w3 = packdup(wv.w);
        const unsigned long long* hp = (const unsigned long long*)&Hs[k * HS_STRIDE + hbase];
#pragma unroll
        for (int p = 0; p < 4; p++) {
            unsigned long long h2 = hp[p];  // {h[r0], h[r1]}
            ffma2(acc[p][0], h2, w0);
            ffma2(acc[p][1], h2, w1);
            ffma2(acc[p][2], h2, w2);
            ffma2(acc[p][3], h2, w3);
        }
    }

    float4 alo = ((const float4*)av)[lane];        // a[0:128]
    float4 ahi = ((const float4*)av)[32 + lane];   // a[128:256]

#pragma unroll
    for (int p = 0; p < 4; p++) {
        float zl[4], zh[4];
#pragma unroll
        for (int c = 0; c < 4; c++) unpack2(acc[p][c], zl[c], zh[c]);
        int r0 = row0 + hbase + 2 * p;
#pragma unroll
        for (int half = 0; half < 2; half++) {
            float* z = half ? zh : zl;
            int row = r0 + half;
            if (row < NN) {
                float4 out4 = make_float4(z[0], z[1], z[2], z[3]);
                *(float4*)&Zout[(size_t)row * DD + lane * 4] = out4;
                float ps = z[0] * alo.x + z[1] * alo.y + z[2] * alo.z + z[3] * alo.w;
                float pd = z[0] * ahi.x + z[1] * ahi.y + z[2] * ahi.z + z[3] * ahi.w;
#pragma unroll
                for (int o = 16; o > 0; o >>= 1) {
                    ps += __shfl_xor_sync(0xFFFFFFFFu, ps, o);
                    pd += __shfl_xor_sync(0xFFFFFFFFu, pd, o);
                }
                if (lane == 0) {
                    Ss[row] = ps;
                    Sd[row] = pd;
                }
            }
        }
    }
}

// ---------------- per-dst-node softmax + aggregation (warp per node) ----------------
__global__ void agg_kernel(const float* __restrict__ Z, const float* __restrict__ Ss,
                           const float* __restrict__ Sd, const int* __restrict__ off,
                           const int* __restrict__ csrsrc, float* __restrict__ esc,
                           float* __restrict__ out, int do_elu) {
    int gw = (blockIdx.x * blockDim.x + threadIdx.x) >> 5;
    int lane = threadIdx.x & 31;
    if (gw >= NN) return;

    int beg = off[gw];
    int end = off[gw + 1];
    int deg = end - beg;

    unsigned long long accA = 0ull, accB = 0ull;

    if (deg > 0) {
        float sd = Sd[gw];
        // phase 1: e = leaky_relu(s_src + s_dst), segment max
        float m = -3.402823466e+38f;
        for (int i = lane; i < deg; i += 32) {
            int s = csrsrc[beg + i];
            float e = Ss[s] + sd;
            e = e > 0.f ? e : 0.01f * e;
            esc[beg + i] = e;
            m = fmaxf(m, e);
        }
#pragma unroll
        for (int o = 16; o > 0; o >>= 1) m = fmaxf(m, __shfl_xor_sync(0xFFFFFFFFu, m, o));

        // phase 2: exp(e - m), segment sum
        float sum = 0.f;
        for (int i = lane; i < deg; i += 32) {
            float ex = __expf(esc[beg + i] - m);
            esc[beg + i] = ex;
            sum += ex;
        }
#pragma unroll
        for (int o = 16; o > 0; o >>= 1) sum += __shfl_xor_sync(0xFFFFFFFFu, sum, o);
        float inv = 1.0f / sum;
        __syncwarp();  // make all lanes' esc stores visible warp-wide

        // phase 3: out += alpha * z[src], features across lanes
        for (int i = 0; i < deg; i++) {
            float a = esc[beg + i] * inv;
            int s = csrsrc[beg + i];
            ulonglong2 zv = *(const ulonglong2*)(Z + (size_t)s * DD + lane * 4);
            unsigned long long ad = packdup(a);
            ffma2(accA, ad, zv.x);
            ffma2(accB, ad, zv.y);
        }
    }

    float o0, o1, o2, o3;
    unpack2(accA, o0, o1);
    unpack2(accB, o2, o3);
    if (do_elu) {
        o0 = elu1(o0); o1 = elu1(o1); o2 = elu1(o2); o3 = elu1(o3);
    }
    *(float4*)&out[(size_t)gw * DD + lane * 4] = make_float4(o0, o1, o2, o3);
}

// ---------------- mean readout: column sums ----------------
__global__ void colsum_kernel(const float* __restrict__ X, float* __restrict__ gsum) {
    int col = threadIdx.x;  // 128 threads
    float s = 0.f;
    for (int r = blockIdx.x; r < NN; r += gridDim.x)
        s += X[(size_t)r * DD + col];
    atomicAdd(&gsum[col], s);
}

// ---------------- final MLP readout (1 block) ----------------
__global__ void mlp_kernel(const float* __restrict__ gsum,
                           const float* __restrict__ M0w, const float* __restrict__ M0b,
                           const float* __restrict__ M1w, const float* __restrict__ M1b,
                           const float* __restrict__ M2w, const float* __restrict__ M2b,
                           float* __restrict__ out) {
    __shared__ float hg[128], y0[64], y1[32];
    int t = threadIdx.x;  // 128 threads
    hg[t] = gsum[t] * (1.0f / (float)NN);
    __syncthreads();
    if (t < 64) {
        float s = M0b[t];
        for (int k = 0; k < 128; k++) s += hg[k] * M0w[k * 64 + t];
        y0[t] = fmaxf(s, 0.f);
    }
    __syncthreads();
    if (t < 32) {
        float s = M1b[t];
        for (int k = 0; k < 64; k++) s += y0[k] * M1w[k * 32 + t];
        y1[t] = fmaxf(s, 0.f);
    }
    __syncthreads();
    if (t < 3) {
        float s = M2b[t];
        for (int k = 0; k < 32; k++) s += y1[k] * M2w[k * 3 + t];
        out[t] = s;
    }
}

// ---------------- host ----------------
extern "C" void kernel_launch(void* const* d_in, const int* in_sizes, int n_in,
                              void* d_out, int out_size) {
    const float* h   = (const float*)d_in[0];
    const int*   src = (const int*)d_in[1];
    const int*   dst = (const int*)d_in[2];
    const float* W0  = (const float*)d_in[3];
    const float* a0  = (const float*)d_in[4];
    const float* W1  = (const float*)d_in[5];
    const float* a1  = (const float*)d_in[6];
    const float* W2  = (const float*)d_in[7];
    const float* a2  = (const float*)d_in[8];
    const float* M0w = (const float*)d_in[9];
    const float* M0b = (const float*)d_in[10];
    const float* M1w = (const float*)d_in[11];
    const float* M1b = (const float*)d_in[12];
    const float* M2w = (const float*)d_in[13];
    const float* M2b = (const float*)d_in[14];
    float* out = (float*)d_out;

    float *Z, *X, *Y, *Ss, *Sd, *esc, *gsum;
    int *deg, *cur, *off, *csrsrc;
    cudaGetSymbolAddress((void**)&Z, d_Z);
    cudaGetSymbolAddress((void**)&X, d_X);
    cudaGetSymbolAddress((void**)&Y, d_Y);
    cudaGetSymbolAddress((void**)&Ss, d_Ssrc);
    cudaGetSymbolAddress((void**)&Sd, d_Sdst);
    cudaGetSymbolAddress((void**)&esc, d_esc);
    cudaGetSymbolAddress((void**)&gsum, d_gsum);
    cudaGetSymbolAddress((void**)&deg, d_deg);
    cudaGetSymbolAddress((void**)&cur, d_cur);
    cudaGetSymbolAddress((void**)&off, d_off);
    cudaGetSymbolAddress((void**)&csrsrc, d_csrsrc);

    cudaFuncSetAttribute(gemm_kernel, cudaFuncAttributeMaxDynamicSharedMemorySize,
                         GEMM_SMEM_BYTES);

    const int TPB = 256;
    init_kernel<<<(NN + TPB - 1) / TPB, TPB>>>(deg, gsum);
    hist_kernel<<<(NE + TPB - 1) / TPB, TPB>>>(dst, deg);
    scan_kernel<<<1, 1024>>>(deg, off, cur);
    scatter_kernel<<<(NE + TPB - 1) / TPB, TPB>>>(src, dst, cur, csrsrc);

    const int GEMM_BLKS = (NN + 63) / 64;
    const int AGG_BLKS = (NN * 32 + TPB - 1) / TPB;

    // layer 0: input h -> X (with ELU)
    gemm_kernel<<<GEMM_BLKS, TPB, GEMM_SMEM_BYTES>>>(h, W0, a0, Z, Ss, Sd);
    agg_kernel<<<AGG_BLKS, TPB>>>(Z, Ss, Sd, off, csrsrc, esc, X, 1);
    // layer 1: X -> Y (with ELU)
    gemm_kernel<<<GEMM_BLKS, TPB, GEMM_SMEM_BYTES>>>(X, W1, a1, Z, Ss, Sd);
    agg_kernel<<<AGG_BLKS, TPB>>>(Z, Ss, Sd, off, csrsrc, esc, Y, 1);
    // layer 2: Y -> X (no ELU)
    gemm_kernel<<<GEMM_BLKS, TPB, GEMM_SMEM_BYTES>>>(Y, W2, a2, Z, Ss, Sd);
    agg_kernel<<<AGG_BLKS, TPB>>>(Z, Ss, Sd, off, csrsrc, esc, X, 0);

    colsum_kernel<<<256, 128>>>(X, gsum);
    mlp_kernel<<<1, 128>>>(gsum, M0w, M0b, M1w, M1b, M2w, M2b, out);
}

// round 3
// speedup vs baseline: 1.0279x; 1.0279x over previous
#include <cuda_runtime.h>
#include <cuda_fp16.h>

#define NN 50000
#define NE 800000
#define DD 128

// ---------------- scratch (__device__ globals; no allocation allowed) ----------------
__device__ __half d_Zh[(size_t)NN * DD];   // z = x @ W for current layer (fp16 for gathers)
__device__ float d_X[(size_t)NN * DD];     // layer outputs ping
__device__ float d_Y[(size_t)NN * DD];     // layer outputs pong
__device__ float d_Ssrc[NN];
__device__ float d_Sdst[NN];
__device__ float d_esc[NE];                // per-edge scratch (fallback path only)
__device__ int   d_deg[NN];
__device__ int   d_cur[NN];
__device__ int   d_off[NN + 1];
__device__ int   d_csrsrc[NE];             // src node per CSR slot (grouped by dst)
__device__ float d_gsum[DD];

// ---------------- helpers ----------------
__device__ __forceinline__ unsigned long long packdup(float x) {
    unsigned long long r;
    asm("mov.b64 %0,{%1,%1};" : "=l"(r) : "f"(x));
    return r;
}
__device__ __forceinline__ void unpack2(unsigned long long v, float& x, float& y) {
    asm("mov.b64 {%0,%1},%2;" : "=f"(x), "=f"(y) : "l"(v));
}
__device__ __forceinline__ void ffma2(unsigned long long& d, unsigned long long a, unsigned long long b) {
    asm("fma.rn.f32x2 %0,%1,%2,%0;" : "+l"(d) : "l"(a), "l"(b));
}
__device__ __forceinline__ float elu1(float x) {
    return x > 0.f ? x : expm1f(x);
}

// ---------------- CSR build ----------------
__global__ void hist_kernel(const int* __restrict__ dst, int* __restrict__ deg) {
    int e = blockIdx.x * blockDim.x + threadIdx.x;
    if (e < NE) atomicAdd(&deg[dst[e]], 1);
}

__global__ void scan_kernel(const int* __restrict__ deg, int* __restrict__ off, int* __restrict__ cur) {
    __shared__ int ssum[1024];
    int t = threadIdx.x;
    const int CH = 49;  // 1024*49 = 50176 >= 50000
    int base = t * CH;
    int s = 0;
#pragma unroll 7
    for (int i = 0; i < CH; i++) {
        int idx = base + i;
        if (idx < NN) s += deg[idx];
    }
    ssum[t] = s;
    __syncthreads();
    int own = s;
    for (int o = 1; o < 1024; o <<= 1) {
        int v = (t >= o) ? ssum[t - o] : 0;
        __syncthreads();
        ssum[t] += v;
        __syncthreads();
    }
    int run = ssum[t] - own;  // exclusive prefix at chunk start
    for (int i = 0; i < CH; i++) {
        int idx = base + i;
        if (idx < NN) {
            off[idx] = run;
            cur[idx] = run;
            run += deg[idx];
        }
    }
    if (t == 1023) off[NN] = ssum[1023];
}

__global__ void scatter_kernel(const int* __restrict__ src, const int* __restrict__ dst,
                               int* __restrict__ cur, int* __restrict__ csrsrc) {
    int e = blockIdx.x * blockDim.x + threadIdx.x;
    if (e < NE) {
        int p = atomicAdd(&cur[dst[e]], 1);
        csrsrc[p] = src[e];
    }
}

// ---------------- GEMM: Z = Hin @ W (stored fp16), s_src/s_dst = Z @ a ----------------
#define HS_STRIDE 66
#define GEMM_SMEM_FLOATS (16384 + DD * HS_STRIDE)
#define GEMM_SMEM_BYTES (GEMM_SMEM_FLOATS * 4)

__global__ void gemm_kernel(const float* __restrict__ Hin, const float* __restrict__ W,
                            const float* __restrict__ av, __half* __restrict__ Zout,
                            float* __restrict__ Ss, float* __restrict__ Sd) {
    extern __shared__ float sm[];
    float* Ws = sm;                 // [128][128]
    float* Hs = sm + 16384;         // [k][row], stride HS_STRIDE

    int tid = threadIdx.x;
    int lane = tid & 31;
    int w = tid >> 5;

    for (int i = tid; i < 4096; i += 256)
        ((float4*)Ws)[i] = ((const float4*)W)[i];

    int row0 = blockIdx.x * 64;
    for (int i = tid; i < 8192; i += 256) {
        int r = i >> 7;
        int k = i & 127;
        int row = row0 + r;
        Hs[k * HS_STRIDE + r] = (row < NN) ? Hin[(size_t)row * DD + k] : 0.f;
    }
    __syncthreads();

    unsigned long long acc[4][4];
#pragma unroll
    for (int p = 0; p < 4; p++)
#pragma unroll
        for (int c = 0; c < 4; c++) acc[p][c] = 0ull;

    int hbase = w * 8;
#pragma unroll 4
    for (int k = 0; k < 128; k++) {
        float4 wv = *(float4*)&Ws[k * DD + lane * 4];
        unsigned long long w0 = packdup(wv.x);
        unsigned long long w1 = packdup(wv.y);
        unsigned long long w2 = packdup(wv.z);
        unsigned long long w3 = packdup(wv.w);
        const unsigned long long* hp = (const unsigned long long*)&Hs[k * HS_STRIDE + hbase];
#pragma unroll
        for (int p = 0; p < 4; p++) {
            unsigned long long h2 = hp[p];
            ffma2(acc[p][0], h2, w0);
            ffma2(acc[p][1], h2, w1);
            ffma2(acc[p][2], h2, w2);
            ffma2(acc[p][3], h2, w3);
        }
    }

    float4 alo = ((const float4*)av)[lane];
    float4 ahi = ((const float4*)av)[32 + lane];

#pragma unroll
    for (int p = 0; p < 4; p++) {
        float zl[4], zh[4];
#pragma unroll
        for (int c = 0; c < 4; c++) unpack2(acc[p][c], zl[c], zh[c]);
        int r0 = row0 + hbase + 2 * p;
#pragma unroll
        for (int half = 0; half < 2; half++) {
            float* z = half ? zh : zl;
            int row = r0 + half;
            if (row < NN) {
                // fp16 Z for the aggregation gathers
                __half2 p0 = __floats2half2_rn(z[0], z[1]);
                __half2 p1 = __floats2half2_rn(z[2], z[3]);
                uint2 pk;
                pk.x = *(unsigned int*)&p0;
                pk.y = *(unsigned int*)&p1;
                *(uint2*)&Zout[(size_t)row * DD + lane * 4] = pk;
                float ps = z[0] * alo.x + z[1] * alo.y + z[2] * alo.z + z[3] * alo.w;
                float pd = z[0] * ahi.x + z[1] * ahi.y + z[2] * ahi.z + z[3] * ahi.w;
#pragma unroll
                for (int o = 16; o > 0; o >>= 1) {
                    ps += __shfl_xor_sync(0xFFFFFFFFu, ps, o);
                    pd += __shfl_xor_sync(0xFFFFFFFFu, pd, o);
                }
                if (lane == 0) {
                    Ss[row] = ps;
                    Sd[row] = pd;
                }
            }
        }
    }
}

// ---------------- per-dst-node softmax + aggregation (warp per node) ----------------
#define NCH 4   // register path covers deg <= 128

__global__ void agg_kernel(const __half* __restrict__ Zh, const float* __restrict__ Ss,
                           const float* __restrict__ Sd, const int* __restrict__ off,
                           const int* __restrict__ csrsrc, float* __restrict__ esc,
                           float* __restrict__ out, int do_elu) {
    int gw = (blockIdx.x * blockDim.x + threadIdx.x) >> 5;
    int lane = threadIdx.x & 31;
    if (gw >= NN) return;

    int beg = off[gw];
    int deg = off[gw + 1] - beg;

    float acc0 = 0.f, acc1 = 0.f, acc2 = 0.f, acc3 = 0.f;
    const __half* zbase = Zh + (size_t)lane * 4;

    if (deg > 0) {
        float sd = Sd[gw];
        if (deg <= NCH * 32) {
            // -------- register-resident path --------
            int nch = (deg + 31) >> 5;
            float ereg[NCH];
            int sreg[NCH];
            float m = -3.402823466e+38f;
            for (int j = 0; j < nch; j++) {
                int li = (j << 5) + lane;
                bool valid = li < deg;
                int s = valid ? csrsrc[beg + li] : 0;
                float e = valid ? Ss[s] + sd : -3.402823466e+38f;
                e = e > 0.f ? e : 0.01f * e;
                sreg[j] = s;
                ereg[j] = e;
                m = fmaxf(m, e);
            }
#pragma unroll
            for (int o = 16; o > 0; o >>= 1) m = fmaxf(m, __shfl_xor_sync(0xFFFFFFFFu, m, o));

            float sum = 0.f;
            for (int j = 0; j < nch; j++) {
                float ex = __expf(ereg[j] - m);   // invalid lanes underflow to 0
                ereg[j] = ex;
                sum += ex;
            }
#pragma unroll
            for (int o = 16; o > 0; o >>= 1) sum += __shfl_xor_sync(0xFFFFFFFFu, sum, o);
            float inv = 1.0f / sum;

            for (int j = 0; j < nch; j++) {
                float aj = ereg[j] * inv;
                int sj = sreg[j];
                int cnt = min(32, deg - (j << 5));
#pragma unroll 4
                for (int i = 0; i < cnt; i++) {
                    float a = __shfl_sync(0xFFFFFFFFu, aj, i);
                    int s = __shfl_sync(0xFFFFFFFFu, sj, i);
                    uint2 zv = *(const uint2*)(zbase + (size_t)s * DD);
                    float2 f0 = __half22float2(*(__half2*)&zv.x);
                    float2 f1 = __half22float2(*(__half2*)&zv.y);
                    acc0 = fmaf(a, f0.x, acc0);
                    acc1 = fmaf(a, f0.y, acc1);
                    acc2 = fmaf(a, f1.x, acc2);
                    acc3 = fmaf(a, f1.y, acc3);
                }
            }
        } else {
            // -------- generic fallback (deg > 128) --------
            float m = -3.402823466e+38f;
            for (int i = lane; i < deg; i += 32) {
                int s = csrsrc[beg + i];
                float e = Ss[s] + sd;
                e = e > 0.f ? e : 0.01f * e;
                esc[beg + i] = e;
                m = fmaxf(m, e);
            }
#pragma unroll
            for (int o = 16; o > 0; o >>= 1) m = fmaxf(m, __shfl_xor_sync(0xFFFFFFFFu, m, o));
            float sum = 0.f;
            for (int i = lane; i < deg; i += 32) {
                float ex = __expf(esc[beg + i] - m);
                esc[beg + i] = ex;
                sum += ex;
            }
#pragma unroll
            for (int o = 16; o > 0; o >>= 1) sum += __shfl_xor_sync(0xFFFFFFFFu, sum, o);
            float inv = 1.0f / sum;
            __syncwarp();
            for (int i = 0; i < deg; i++) {
                float a = esc[beg + i] * inv;
                int s = csrsrc[beg + i];
                uint2 zv = *(const uint2*)(zbase + (size_t)s * DD);
                float2 f0 = __half22float2(*(__half2*)&zv.x);
                float2 f1 = __half22float2(*(__half2*)&zv.y);
                acc0 = fmaf(a, f0.x, acc0);
                acc1 = fmaf(a, f0.y, acc1);
                acc2 = fmaf(a, f1.x, acc2);
                acc3 = fmaf(a, f1.y, acc3);
            }
        }
    }

    if (do_elu) {
        acc0 = elu1(acc0); acc1 = elu1(acc1); acc2 = elu1(acc2); acc3 = elu1(acc3);
    }
    *(float4*)&out[(size_t)gw * DD + lane * 4] = make_float4(acc0, acc1, acc2, acc3);
}

// ---------------- mean readout: column sums ----------------
__global__ void colsum_kernel(const float* __restrict__ X, float* __restrict__ gsum) {
    int col = threadIdx.x;  // 128 threads
    float s = 0.f;
    for (int r = blockIdx.x; r < NN; r += gridDim.x)
        s += X[(size_t)r * DD + col];
    atomicAdd(&gsum[col], s);
}

// ---------------- final MLP readout (1 block) ----------------
__global__ void mlp_kernel(const float* __restrict__ gsum,
                           const float* __restrict__ M0w, const float* __restrict__ M0b,
                           const float* __restrict__ M1w, const float* __restrict__ M1b,
                           const float* __restrict__ M2w, const float* __restrict__ M2b,
                           float* __restrict__ out) {
    __shared__ float hg[128], y0[64], y1[32];
    int t = threadIdx.x;  // 128 threads
    hg[t] = gsum[t] * (1.0f / (float)NN);
    __syncthreads();
    if (t < 64) {
        float s = M0b[t];
        for (int k = 0; k < 128; k++) s += hg[k] * M0w[k * 64 + t];
        y0[t] = fmaxf(s, 0.f);
    }
    __syncthreads();
    if (t < 32) {
        float s = M1b[t];
        for (int k = 0; k < 64; k++) s += y0[k] * M1w[k * 32 + t];
        y1[t] = fmaxf(s, 0.f);
    }
    __syncthreads();
    if (t < 3) {
        float s = M2b[t];
        for (int k = 0; k < 32; k++) s += y1[k] * M2w[k * 3 + t];
        out[t] = s;
    }
}

// ---------------- host ----------------
extern "C" void kernel_launch(void* const* d_in, const int* in_sizes, int n_in,
                              void* d_out, int out_size) {
    const float* h   = (const float*)d_in[0];
    const int*   src = (const int*)d_in[1];
    const int*   dst = (const int*)d_in[2];
    const float* W0  = (const float*)d_in[3];
    const float* a0  = (const float*)d_in[4];
    const float* W1  = (const float*)d_in[5];
    const float* a1  = (const float*)d_in[6];
    const float* W2  = (const float*)d_in[7];
    const float* a2  = (const float*)d_in[8];
    const float* M0w = (const float*)d_in[9];
    const float* M0b = (const float*)d_in[10];
    const float* M1w = (const float*)d_in[11];
    const float* M1b = (const float*)d_in[12];
    const float* M2w = (const float*)d_in[13];
    const float* M2b = (const float*)d_in[14];
    float* out = (float*)d_out;

    __half* Zh;
    float *X, *Y, *Ss, *Sd, *esc, *gsum;
    int *deg, *cur, *off, *csrsrc;
    cudaGetSymbolAddress((void**)&Zh, d_Zh);
    cudaGetSymbolAddress((void**)&X, d_X);
    cudaGetSymbolAddress((void**)&Y, d_Y);
    cudaGetSymbolAddress((void**)&Ss, d_Ssrc);
    cudaGetSymbolAddress((void**)&Sd, d_Sdst);
    cudaGetSymbolAddress((void**)&esc, d_esc);
    cudaGetSymbolAddress((void**)&gsum, d_gsum);
    cudaGetSymbolAddress((void**)&deg, d_deg);
    cudaGetSymbolAddress((void**)&cur, d_cur);
    cudaGetSymbolAddress((void**)&off, d_off);
    cudaGetSymbolAddress((void**)&csrsrc, d_csrsrc);

    cudaFuncSetAttribute(gemm_kernel, cudaFuncAttributeMaxDynamicSharedMemorySize,
                         GEMM_SMEM_BYTES);

    const int TPB = 256;
    cudaMemsetAsync(deg, 0, NN * sizeof(int));
    cudaMemsetAsync(gsum, 0, DD * sizeof(float));
    hist_kernel<<<(NE + TPB - 1) / TPB, TPB>>>(dst, deg);
    scan_kernel<<<1, 1024>>>(deg, off, cur);
    scatter_kernel<<<(NE + TPB - 1) / TPB, TPB>>>(src, dst, cur, csrsrc);

    const int GEMM_BLKS = (NN + 63) / 64;
    const int AGG_BLKS = (NN * 32 + TPB - 1) / TPB;

    // layer 0: input h -> X (with ELU)
    gemm_kernel<<<GEMM_BLKS, TPB, GEMM_SMEM_BYTES>>>(h, W0, a0, Zh, Ss, Sd);
    agg_kernel<<<AGG_BLKS, TPB>>>(Zh, Ss, Sd, off, csrsrc, esc, X, 1);
    // layer 1: X -> Y (with ELU)
    gemm_kernel<<<GEMM_BLKS, TPB, GEMM_SMEM_BYTES>>>(X, W1, a1, Zh, Ss, Sd);
    agg_kernel<<<AGG_BLKS, TPB>>>(Zh, Ss, Sd, off, csrsrc, esc, Y, 1);
    // layer 2: Y -> X (no ELU)
    gemm_kernel<<<GEMM_BLKS, TPB, GEMM_SMEM_BYTES>>>(Y, W2, a2, Zh, Ss, Sd);
    agg_kernel<<<AGG_BLKS, TPB>>>(Zh, Ss, Sd, off, csrsrc, esc, X, 0);

    colsum_kernel<<<256, 128>>>(X, gsum);
    mlp_kernel<<<1, 128>>>(gsum, M0w, M0b, M1w, M1b, M2w, M2b, out);
}